// round 10
// baseline (speedup 1.0000x reference)
#include <cuda_runtime.h>
#include <cuda_fp16.h>
#include <cstdint>
#include <math.h>

#define SEQ    2048
#define DMODEL 5120
#define NHEAD  40
#define HDIM   128
#define NQKV   15360
#define ATT_SCALE 0.08838834764831845f

// ---------------------------------------------------------------------------
// Scratch (device globals — no allocation allowed)
// ---------------------------------------------------------------------------
__device__ __align__(256) float  g_qkv[(size_t)SEQ * NQKV];
__device__ __align__(256) __half g_a1[(size_t)SEQ * DMODEL];        // act hi [M,K]; x then ctx
__device__ __align__(256) __half g_w1[(size_t)NQKV * DMODEL];       // w_qkv^T hi [N,K]
__device__ __align__(256) __half g_w2[(size_t)DMODEL * DMODEL];     // w_out^T hi [N,K]
__device__ __align__(256) __half g_q2[(size_t)NHEAD * SEQ * 256];   // Q [H,S,256] (hi,lo)
__device__ __align__(256) __half g_k2[(size_t)NHEAD * SEQ * 256];   // K [H,S,256] (hi,hi)
__device__ __align__(256) __half g_vt[(size_t)NHEAD * HDIM * SEQ];  // V^T [H,D,S] fp16

// ---------------------------------------------------------------------------
__device__ __forceinline__ uint32_t smem_u32(const void* p) {
    uint32_t a;
    asm("{ .reg .u64 t; cvta.to.shared.u64 t, %1; cvt.u32.u64 %0, t; }" : "=r"(a) : "l"(p));
    return a;
}
#define CP_ASYNC16(dst, src) \
    asm volatile("cp.async.cg.shared.global [%0], [%1], 16;" :: "r"(dst), "l"(src) : "memory")
#define CP_COMMIT()  asm volatile("cp.async.commit_group;" ::: "memory")
#define CP_WAIT1()   asm volatile("cp.async.wait_group 1;" ::: "memory")
#define CP_WAIT0()   asm volatile("cp.async.wait_group 0;" ::: "memory")

#define LDMX4(r0, r1, r2, r3, addr) \
    asm volatile("ldmatrix.sync.aligned.m8n8.x4.shared.b16 {%0,%1,%2,%3}, [%4];" \
        : "=r"(r0), "=r"(r1), "=r"(r2), "=r"(r3) : "r"(addr))

__device__ __forceinline__ void mma16816(float* d, const uint32_t* a, const uint32_t* b) {
    asm volatile(
        "mma.sync.aligned.m16n8k16.row.col.f32.f16.f16.f32 "
        "{%0,%1,%2,%3}, {%4,%5,%6,%7}, {%8,%9}, {%0,%1,%2,%3};"
        : "+f"(d[0]), "+f"(d[1]), "+f"(d[2]), "+f"(d[3])
        : "r"(a[0]), "r"(a[1]), "r"(a[2]), "r"(a[3]), "r"(b[0]), "r"(b[1]));
}

// ---------------------------------------------------------------------------
// conv_act_hi: [M,K] fp32 -> [M,K] fp16 hi
// ---------------------------------------------------------------------------
__global__ __launch_bounds__(256) void conv_act_hi(const float* __restrict__ in,
                                                   __half* __restrict__ out, int n8)
{
    int t = blockIdx.x * 256 + threadIdx.x;
    if (t >= n8) return;
    size_t k = (size_t)t * 8;
    float4 a = *(const float4*)(in + k);
    float4 b = *(const float4*)(in + k + 4);
    __half o[8];
    o[0] = __float2half_rn(a.x); o[1] = __float2half_rn(a.y);
    o[2] = __float2half_rn(a.z); o[3] = __float2half_rn(a.w);
    o[4] = __float2half_rn(b.x); o[5] = __float2half_rn(b.y);
    o[6] = __float2half_rn(b.z); o[7] = __float2half_rn(b.w);
    *(uint4*)(out + k) = *(const uint4*)o;
}

// ---------------------------------------------------------------------------
// conv_wt_hi: [K,N] fp32 -> [N,K] fp16 hi (transpose)
// ---------------------------------------------------------------------------
__global__ __launch_bounds__(128) void conv_wt_hi(const float* __restrict__ W,
                                                  __half* __restrict__ Wt,
                                                  int Kdim, int Ndim)
{
    __shared__ float tile[32][33];
    const int k0 = blockIdx.y * 32, n0 = blockIdx.x * 32;
    const int lane = threadIdx.x & 31, warp = threadIdx.x >> 5;
#pragma unroll
    for (int i = 0; i < 8; i++) {
        int kr = warp + i * 4;
        tile[kr][lane] = W[(size_t)(k0 + kr) * Ndim + n0 + lane];
    }
    __syncthreads();
    const int nl = threadIdx.x >> 2;
    const int ks = threadIdx.x & 3;
    __half o[8];
#pragma unroll
    for (int e = 0; e < 8; e++)
        o[e] = __float2half_rn(tile[ks * 8 + e][nl]);
    *(uint4*)(Wt + (size_t)(n0 + nl) * (size_t)Kdim + k0 + ks * 8) = *(const uint4*)o;
}

// ---------------------------------------------------------------------------
// conv_vt: V [S, d@qkv] fp32 -> V^T [H, D, S] fp16
// ---------------------------------------------------------------------------
__global__ __launch_bounds__(256) void conv_vt()
{
    __shared__ float t[32][33];
    const int s0  = blockIdx.x * 32;
    const int d0g = blockIdx.y * 32;
    const int h   = d0g >> 7;
    const int dh0 = d0g & 127;
    const int lx = threadIdx.x & 31, ly = threadIdx.x >> 5;
    const float* src = g_qkv + 2 * DMODEL + (size_t)h * HDIM + dh0;
#pragma unroll
    for (int r = 0; r < 4; r++) {
        int srow = ly + r * 8;
        t[srow][lx] = src[(size_t)(s0 + srow) * NQKV + lx];
    }
    __syncthreads();
#pragma unroll
    for (int r = 0; r < 4; r++) {
        int dd = ly + r * 8;
        g_vt[(size_t)(d0g + dd) * SEQ + s0 + lx] = __float2half_rn(t[lx][dd]);
    }
}

// ---------------------------------------------------------------------------
// mma.sync GEMM: C[M,N] = A[M,K] x B[N,K]^T + bias
// CTA 128x256, BK=64, 3-stage cp.async, 8 warps (2M x 4N), warp tile 64x64.
// 1 CTA/SM; smem stage = A 16KB + B 32KB = 48KB, 3 stages = 144KB.
// ---------------------------------------------------------------------------
__global__ __launch_bounds__(256, 1) void gemm_mma(
    const __half* __restrict__ A, const __half* __restrict__ B,
    const float* __restrict__ bias, float* __restrict__ C, int N, int K2)
{
    extern __shared__ char smem[];
    const uint32_t sb = smem_u32(smem);
    const int tid = threadIdx.x;
    const int lane = tid & 31;
    const int wid = tid >> 5;
    const int wm = (wid & 1) * 64;          // 2 warp rows
    const int wn = (wid >> 1) * 64;         // 4 warp cols
    const uint32_t SSZ = 49152;             // stage: A 16KB + B 32KB

    const size_t arow0 = (size_t)blockIdx.x * 128;
    const size_t brow0 = (size_t)blockIdx.y * 256;
    const int NC = K2 / 64;

    // --- precomputed cp.async addressing ---
    const int row0 = tid >> 3, c0 = tid & 7;
    const uint32_t off0 = (uint32_t)(row0 * 128) + (((uint32_t)(c0 ^ (row0 & 7))) << 4);
    const __half* srcA0 = A + (arow0 + row0) * (size_t)K2 + c0 * 8;
    const __half* srcB0 = B + (brow0 + row0) * (size_t)K2 + c0 * 8;
    const size_t rstep = (size_t)32 * K2;

    auto load_stage = [&](uint32_t stbase, int kc) {
        const __half* sa = srcA0 + kc * 64;
        const __half* sbp = srcB0 + kc * 64;
#pragma unroll
        for (int i = 0; i < 4; i++)
            CP_ASYNC16(stbase + off0 + (uint32_t)i * 4096u, sa + rstep * i);
#pragma unroll
        for (int i = 0; i < 8; i++)
            CP_ASYNC16(stbase + 16384u + off0 + (uint32_t)i * 4096u, sbp + rstep * i);
    };

    float acc[4][8][4];
#pragma unroll
    for (int t = 0; t < 4; t++)
#pragma unroll
        for (int j = 0; j < 8; j++)
#pragma unroll
            for (int e = 0; e < 4; e++) acc[t][j][e] = 0.f;

    load_stage(sb, 0); CP_COMMIT();
    load_stage(sb + SSZ, 1); CP_COMMIT();

    const int g = lane >> 2;
    const int tig = lane & 3;
    const int lr = lane & 15;
    const uint32_t lc = (uint32_t)(lane >> 4);
    const uint32_t xr = (uint32_t)(lane & 7);
    // fragment row bases (loop invariant)
    uint32_t rowA[4], rowB[4];
#pragma unroll
    for (int t = 0; t < 4; t++)
        rowA[t] = (uint32_t)((wm + 16 * t + lr) * 128);
#pragma unroll
    for (int jj = 0; jj < 4; jj++)
        rowB[jj] = 16384u + (uint32_t)((wn + 16 * jj + lr) * 128);
    uint32_t xcol[4];
#pragma unroll
    for (int ks = 0; ks < 4; ks++)
        xcol[ks] = ((((uint32_t)(2 * ks) + lc) ^ xr) << 4);

    uint32_t curst = 0, pfst = 2;

    for (int cc = 0; cc < NC; cc++) {
        CP_WAIT1();
        __syncthreads();
        if (cc + 2 < NC) load_stage(sb + pfst * SSZ, cc + 2);
        CP_COMMIT();

        const uint32_t sA = sb + curst * SSZ;
#pragma unroll
        for (int ks = 0; ks < 4; ks++) {
            const uint32_t xc = xcol[ks];
            uint32_t a[4][4], b[8][2];
#pragma unroll
            for (int t = 0; t < 4; t++)
                LDMX4(a[t][0], a[t][1], a[t][2], a[t][3], sA + rowA[t] + xc);
#pragma unroll
            for (int jj = 0; jj < 4; jj++)
                LDMX4(b[2 * jj][0], b[2 * jj + 1][0], b[2 * jj][1], b[2 * jj + 1][1],
                      sA + rowB[jj] + xc);
#pragma unroll
            for (int t = 0; t < 4; t++)
#pragma unroll
                for (int j = 0; j < 8; j++)
                    mma16816(acc[t][j], a[t], b[j]);
        }
        __syncthreads();
        curst = (curst == 2) ? 0 : curst + 1;
        pfst  = (pfst == 2) ? 0 : pfst + 1;
    }

#pragma unroll
    for (int t = 0; t < 4; t++) {
        int r = (int)arow0 + wm + t * 16 + g;
#pragma unroll
        for (int j = 0; j < 8; j++) {
            int c = (int)brow0 + wn + j * 8 + tig * 2;
            float bx = bias[c], by = bias[c + 1];
            float2 v0 = {acc[t][j][0] + bx, acc[t][j][1] + by};
            float2 v1 = {acc[t][j][2] + bx, acc[t][j][3] + by};
            *(float2*)(C + (size_t)r * N + c) = v0;
            *(float2*)(C + (size_t)(r + 8) * N + c) = v1;
        }
    }
}

// ---------------------------------------------------------------------------
// RMSNorm + RoPE -> fp16 Q' (hi,lo) and K' (hi,hi), layout [H,S,256]
// ---------------------------------------------------------------------------
__global__ __launch_bounds__(256) void norm_rope(
    const float* __restrict__ cosp, const float* __restrict__ sinp,
    const float* __restrict__ wq, const float* __restrict__ wk)
{
    const int s = blockIdx.x;
    const int tid = threadIdx.x;
    const float* qrow = g_qkv + (size_t)s * NQKV;
    const float* krow = qrow + DMODEL;

    float sq = 0.f, sk = 0.f;
    for (int i = tid; i < DMODEL; i += 256) {
        float a = qrow[i]; sq += a * a;
        float b = krow[i]; sk += b * b;
    }
#pragma unroll
    for (int off = 16; off; off >>= 1) {
        sq += __shfl_xor_sync(0xffffffffu, sq, off);
        sk += __shfl_xor_sync(0xffffffffu, sk, off);
    }
    __shared__ float shq[8], shk[8];
    if ((tid & 31) == 0) { shq[tid >> 5] = sq; shk[tid >> 5] = sk; }
    __syncthreads();
    float tq = 0.f, tk = 0.f;
#pragma unroll
    for (int i = 0; i < 8; i++) { tq += shq[i]; tk += shk[i]; }
    const float rq = rsqrtf(tq / DMODEL + 1e-6f);
    const float rk = rsqrtf(tk / DMODEL + 1e-6f);

    for (int p = tid; p < DMODEL / 2; p += 256) {
        const int i0 = 2 * p;
        const int h = i0 >> 7;
        const int dl = i0 & 127;
        const float c  = cosp[s * HDIM + dl];
        const float sn = sinp[s * HDIM + dl];
        float q0 = qrow[i0] * rq * wq[i0];
        float q1 = qrow[i0 + 1] * rq * wq[i0 + 1];
        float k0 = krow[i0] * rk * wk[i0];
        float k1 = krow[i0 + 1] * rk * wk[i0 + 1];
        float qe = q0 * c - q1 * sn;
        float qo = q0 * sn + q1 * c;
        float ke = k0 * c - k1 * sn;
        float ko = k0 * sn + k1 * c;

        const size_t base = ((size_t)h * SEQ + s) * 256 + 2 * dl;
        __half qeh = __float2half_rn(qe);
        __half qel = __float2half_rn(qe - __half2float(qeh));
        __half qoh = __float2half_rn(qo);
        __half qol = __float2half_rn(qo - __half2float(qoh));
        __half qv[4] = {qeh, qel, qoh, qol};
        *(uint2*)(g_q2 + base) = *(const uint2*)qv;

        __half keh = __float2half_rn(ke);
        __half koh = __float2half_rn(ko);
        __half kv[4] = {keh, keh, koh, koh};
        *(uint2*)(g_k2 + base) = *(const uint2*)kv;
    }
}

// ---------------------------------------------------------------------------
// Tensor-core flash attention (ldmatrix). CTA: 64 q x 1 head, 4 warps.
// smem: Q' 32KB @0, K' 32KB @32768, Vt 16KB @65536. Total 81920.
// Epilogue: ctx hi-only fp16 into g_a1 [S, DMODEL].
// ---------------------------------------------------------------------------
__global__ __launch_bounds__(128, 2) void flash_tc()
{
    extern __shared__ char smem[];
    const uint32_t sb = smem_u32(smem);
    const int h  = blockIdx.y;
    const int qt = blockIdx.x;
    const int tid = threadIdx.x;
    const int lane = tid & 31;
    const int wid = tid >> 5;
    const int g = lane >> 2;
    const int tig = lane & 3;
    const int lr = lane & 15;
    const uint32_t lc = (uint32_t)(lane >> 4);
    const uint32_t xr = (uint32_t)(lane & 7);

    const __half* Qg = g_q2 + ((size_t)h * SEQ + qt * 64) * 256;
    const __half* Kg = g_k2 + (size_t)h * SEQ * 256;
    const __half* Vg = g_vt + (size_t)h * HDIM * SEQ;

    // load Q' once
#pragma unroll
    for (int i = 0; i < 16; i++) {
        int id = tid + i * 128;
        int r = id >> 5, c = id & 31;
        uint32_t dst = sb + (uint32_t)(r * 512) + (((uint32_t)(c ^ (r & 7))) << 4);
        CP_ASYNC16(dst, Qg + (size_t)r * 256 + c * 8);
    }
    CP_COMMIT();

    const uint32_t rowQ = (uint32_t)((wid * 16 + lr) * 512);
    uint32_t rowK[4], rowV[8];
#pragma unroll
    for (int jj = 0; jj < 4; jj++)
        rowK[jj] = 32768u + (uint32_t)((16 * jj + lr) * 512);
#pragma unroll
    for (int jj = 0; jj < 8; jj++)
        rowV[jj] = 65536u + (uint32_t)((16 * jj + lr) * 128);
    uint32_t xcol[4];
#pragma unroll
    for (int kk = 0; kk < 4; kk++)
        xcol[kk] = ((((uint32_t)(2 * kk) + lc) ^ xr) << 4);

    float o[16][4];
#pragma unroll
    for (int jd = 0; jd < 16; jd++)
#pragma unroll
        for (int e = 0; e < 4; e++) o[jd][e] = 0.f;
    float mA = -1e30f, mB = -1e30f, lA = 0.f, lB = 0.f;

    for (int kt = 0; kt < SEQ / 64; kt++) {
        __syncthreads();
#pragma unroll
        for (int i = 0; i < 16; i++) {
            int id = tid + i * 128;
            int r = id >> 5, c = id & 31;
            uint32_t dst = sb + 32768u + (uint32_t)(r * 512) + (((uint32_t)(c ^ (r & 7))) << 4);
            CP_ASYNC16(dst, Kg + (size_t)(kt * 64 + r) * 256 + c * 8);
        }
#pragma unroll
        for (int i = 0; i < 8; i++) {
            int id = tid + i * 128;
            int r = id >> 3, c = id & 7;
            uint32_t dst = sb + 65536u + (uint32_t)(r * 128) + (((uint32_t)(c ^ (r & 7))) << 4);
            CP_ASYNC16(dst, Vg + (size_t)r * SEQ + kt * 64 + c * 8);
        }
        CP_COMMIT();
        CP_WAIT0();
        __syncthreads();

        // ---- S = Q' K'^T (k-dim 256) ----
        float sacc[8][4];
#pragma unroll
        for (int j = 0; j < 8; j++)
#pragma unroll
            for (int e = 0; e < 4; e++) sacc[j][e] = 0.f;

#pragma unroll
        for (int ks = 0; ks < 16; ks++) {
            const uint32_t xc = ((((uint32_t)(2 * ks) + lc) ^ xr) << 4);
            uint32_t a[4], b[8][2];
            LDMX4(a[0], a[1], a[2], a[3], sb + rowQ + xc);
#pragma unroll
            for (int jj = 0; jj < 4; jj++)
                LDMX4(b[2 * jj][0], b[2 * jj + 1][0], b[2 * jj][1], b[2 * jj + 1][1],
                      sb + rowK[jj] + xc);
#pragma unroll
            for (int j = 0; j < 8; j++)
                mma16816(sacc[j], a, b[j]);
        }

        // ---- online softmax ----
        float mxA = -1e30f, mxB = -1e30f;
#pragma unroll
        for (int j = 0; j < 8; j++) {
            sacc[j][0] *= ATT_SCALE; sacc[j][1] *= ATT_SCALE;
            sacc[j][2] *= ATT_SCALE; sacc[j][3] *= ATT_SCALE;
            mxA = fmaxf(mxA, fmaxf(sacc[j][0], sacc[j][1]));
            mxB = fmaxf(mxB, fmaxf(sacc[j][2], sacc[j][3]));
        }
        mxA = fmaxf(mxA, __shfl_xor_sync(0xffffffffu, mxA, 1));
        mxA = fmaxf(mxA, __shfl_xor_sync(0xffffffffu, mxA, 2));
        mxB = fmaxf(mxB, __shfl_xor_sync(0xffffffffu, mxB, 1));
        mxB = fmaxf(mxB, __shfl_xor_sync(0xffffffffu, mxB, 2));
        const float mnA = fmaxf(mA, mxA);
        const float mnB = fmaxf(mB, mxB);
        const float fsA = __expf(mA - mnA);
        const float fsB = __expf(mB - mnB);
        float psA = 0.f, psB = 0.f;
        uint32_t pA[8], pB[8];
#pragma unroll
        for (int j = 0; j < 8; j++) {
            float p0 = __expf(sacc[j][0] - mnA);
            float p1 = __expf(sacc[j][1] - mnA);
            float p2 = __expf(sacc[j][2] - mnB);
            float p3 = __expf(sacc[j][3] - mnB);
            psA += p0 + p1; psB += p2 + p3;
            __half2 hA = __floats2half2_rn(p0, p1);
            __half2 hB = __floats2half2_rn(p2, p3);
            pA[j] = *(uint32_t*)&hA;
            pB[j] = *(uint32_t*)&hB;
        }
        psA += __shfl_xor_sync(0xffffffffu, psA, 1);
        psA += __shfl_xor_sync(0xffffffffu, psA, 2);
        psB += __shfl_xor_sync(0xffffffffu, psB, 1);
        psB += __shfl_xor_sync(0xffffffffu, psB, 2);
        lA = lA * fsA + psA;
        lB = lB * fsB + psB;
        mA = mnA; mB = mnB;
#pragma unroll
        for (int jd = 0; jd < 16; jd++) {
            o[jd][0] *= fsA; o[jd][1] *= fsA;
            o[jd][2] *= fsB; o[jd][3] *= fsB;
        }

        // ---- O += P V^T ----
#pragma unroll
        for (int kk = 0; kk < 4; kk++) {
            uint32_t a2[4] = {pA[2 * kk], pB[2 * kk], pA[2 * kk + 1], pB[2 * kk + 1]};
            const uint32_t xc = xcol[kk];
            uint32_t bv[16][2];
#pragma unroll
            for (int jj = 0; jj < 8; jj++)
                LDMX4(bv[2 * jj][0], bv[2 * jj + 1][0], bv[2 * jj][1], bv[2 * jj + 1][1],
                      sb + rowV[jj] + xc);
#pragma unroll
            for (int jd = 0; jd < 16; jd++)
                mma16816(o[jd], a2, bv[jd]);
        }
    }

    // ---- epilogue: ctx hi-only fp16 into g_a1 [S, DMODEL] ----
    const float invA = 1.0f / lA;
    const float invB = 1.0f / lB;
    const int rA = qt * 64 + wid * 16 + g;
    const int rB = rA + 8;
#pragma unroll
    for (int jd = 0; jd < 16; jd++) {
        const int c = 8 * jd + 2 * tig;
        const size_t col = (size_t)h * HDIM + c;
        __half2 ha = __floats2half2_rn(o[jd][0] * invA, o[jd][1] * invA);
        __half2 hb = __floats2half2_rn(o[jd][2] * invB, o[jd][3] * invB);
        *(__half2*)(g_a1 + (size_t)rA * DMODEL + col) = ha;
        *(__half2*)(g_a1 + (size_t)rB * DMODEL + col) = hb;
    }
}

// ---------------------------------------------------------------------------
extern "C" void kernel_launch(void* const* d_in, const int* in_sizes, int n_in,
                              void* d_out, int out_size)
{
    const float* x     = (const float*)d_in[0];
    const float* cosp  = (const float*)d_in[1];
    const float* sinp  = (const float*)d_in[2];
    const float* w_qkv = (const float*)d_in[3];
    const float* b_qkv = (const float*)d_in[4];
    const float* wq    = (const float*)d_in[5];
    const float* wk    = (const float*)d_in[6];
    const float* w_out = (const float*)d_in[7];
    const float* b_out = (const float*)d_in[8];
    float* out = (float*)d_out;

    float* qkv_p;
    __half *a1_p, *w1_p, *w2_p;
    cudaGetSymbolAddress((void**)&qkv_p, g_qkv);
    cudaGetSymbolAddress((void**)&a1_p,  g_a1);
    cudaGetSymbolAddress((void**)&w1_p,  g_w1);
    cudaGetSymbolAddress((void**)&w2_p,  g_w2);

    const int GEMM_SMEM = 3 * 49152;   // 147456
    cudaFuncSetAttribute(gemm_mma, cudaFuncAttributeMaxDynamicSharedMemorySize, GEMM_SMEM);
    cudaFuncSetAttribute(flash_tc, cudaFuncAttributeMaxDynamicSharedMemorySize, 81920);

    // conversions (hi-only everywhere)
    conv_wt_hi<<<dim3(NQKV / 32, DMODEL / 32), 128>>>(w_qkv, w1_p, DMODEL, NQKV);
    conv_wt_hi<<<dim3(DMODEL / 32, DMODEL / 32), 128>>>(w_out, w2_p, DMODEL, DMODEL);
    conv_act_hi<<<(SEQ * DMODEL / 8 + 255) / 256, 256>>>(x, a1_p, SEQ * DMODEL / 8);

    // QKV projection: K=5120, CTA 128x256
    gemm_mma<<<dim3(SEQ / 128, NQKV / 256), 256, GEMM_SMEM>>>(
        a1_p, w1_p, b_qkv, qkv_p, NQKV, DMODEL);

    // RMSNorm + RoPE; V transpose
    norm_rope<<<SEQ, 256>>>(cosp, sinp, wq, wk);
    conv_vt<<<dim3(SEQ / 32, DMODEL / 32), 256>>>();

    // tensor-core attention (writes ctx hi into g_a1)
    flash_tc<<<dim3(SEQ / 64, NHEAD), 128, 81920>>>();

    // output projection: K=5120, CTA 128x256
    gemm_mma<<<dim3(SEQ / 128, DMODEL / 256), 256, GEMM_SMEM>>>(
        a1_p, w2_p, b_out, out, DMODEL, DMODEL);
}